// round 6
// baseline (speedup 1.0000x reference)
#include <cuda_runtime.h>
#include <cuda_bf16.h>
#include <cstdint>
#include <math.h>

// Problem constants
#define BSZ 32
#define LSEQ 4096
#define DIM 256
#define GDIM 768   // 3*DIM

// ---------------- scratch (device globals; no allocation allowed) ----------
__device__ float g_emb[BSZ * (LSEQ/2) * DIM];
__device__ float g_hs [BSZ * (LSEQ/2) * DIM];
__device__ float g_h0 [BSZ * (LSEQ/2) * DIM];
__device__ float g_h1 [BSZ * (LSEQ/2) * DIM];
__device__ float g_GI [(size_t)BSZ * LSEQ * GDIM];
__device__ float g_GH [(size_t)BSZ * (LSEQ/2) * GDIM];

// bf16 split operand buffers
__device__ __nv_bfloat16 g_lhi[(size_t)BSZ * LSEQ * DIM];
__device__ __nv_bfloat16 g_llo[(size_t)BSZ * LSEQ * DIM];
__device__ __nv_bfloat16 g_ehi[(size_t)BSZ * (LSEQ/2) * DIM];
__device__ __nv_bfloat16 g_elo[(size_t)BSZ * (LSEQ/2) * DIM];
__device__ __nv_bfloat16 g_h0hi[(size_t)BSZ * (LSEQ/2) * DIM];
__device__ __nv_bfloat16 g_h0lo[(size_t)BSZ * (LSEQ/2) * DIM];
__device__ __nv_bfloat16 g_h1hi[(size_t)BSZ * (LSEQ/2) * DIM];
__device__ __nv_bfloat16 g_h1lo[(size_t)BSZ * (LSEQ/2) * DIM];
__device__ __nv_bfloat16 g_wihhi[GDIM * DIM], g_wihlo[GDIM * DIM];
__device__ __nv_bfloat16 g_whhhi[GDIM * DIM], g_whhlo[GDIM * DIM];

// ======================= helpers ==========================
__device__ __forceinline__ uint32_t smem_u32(const void* p) {
    uint32_t a;
    asm("{ .reg .u64 t; cvta.to.shared.u64 t, %1; cvt.u32.u64 %0, t; }"
        : "=r"(a) : "l"(p));
    return a;
}

__device__ __forceinline__ uint32_t swz(uint32_t b) { return b ^ ((b >> 3) & 0x70); }

__device__ __forceinline__ void cp16(uint32_t dst, const void* src, int sz) {
    asm volatile("cp.async.cg.shared.global [%0], [%1], 16, %2;"
                 :: "r"(dst), "l"(src), "r"(sz));
}

#define CP_COMMIT() asm volatile("cp.async.commit_group;" ::: "memory")
#define CP_WAIT0()  asm volatile("cp.async.wait_group 0;" ::: "memory")

#define LDSM4(R, addr) \
    asm volatile("ldmatrix.sync.aligned.m8n8.x4.shared.b16 {%0,%1,%2,%3}, [%4];" \
        : "=r"((R)[0]), "=r"((R)[1]), "=r"((R)[2]), "=r"((R)[3]) : "r"(addr))

#define MMA_BF16(C, A, B0, B1) \
    asm volatile("mma.sync.aligned.m16n8k16.row.col.f32.bf16.bf16.f32 " \
        "{%0,%1,%2,%3},{%4,%5,%6,%7},{%8,%9},{%0,%1,%2,%3};" \
        : "+f"((C)[0]), "+f"((C)[1]), "+f"((C)[2]), "+f"((C)[3]) \
        : "r"((A)[0]), "r"((A)[1]), "r"((A)[2]), "r"((A)[3]), "r"(B0), "r"(B1))

__device__ __forceinline__ void split1(float x, unsigned short& h, unsigned short& l) {
    __nv_bfloat16 hb = __float2bfloat16(x);
    float resid = x - __bfloat162float(hb);
    __nv_bfloat16 lb = __float2bfloat16(resid);
    h = __bfloat16_as_ushort(hb);
    l = __bfloat16_as_ushort(lb);
}

__device__ __forceinline__ void split_store4(float4 v,
    __nv_bfloat16* __restrict__ hi, __nv_bfloat16* __restrict__ lo, size_t idx)
{
    unsigned short h[4], l[4];
    split1(v.x, h[0], l[0]); split1(v.y, h[1], l[1]);
    split1(v.z, h[2], l[2]); split1(v.w, h[3], l[3]);
    uint2 hv = make_uint2((uint32_t)h[0] | ((uint32_t)h[1] << 16),
                          (uint32_t)h[2] | ((uint32_t)h[3] << 16));
    uint2 lv = make_uint2((uint32_t)l[0] | ((uint32_t)l[1] << 16),
                          (uint32_t)l[2] | ((uint32_t)l[3] << 16));
    *(uint2*)(hi + idx) = hv;
    *(uint2*)(lo + idx) = lv;
}

// ======================= tensor-core GEMM (mma.sync bf16 split) =============
// C[M,768] = A[M,256] @ W[768,256]^T,  A/W pre-split bf16 hi/lo.
// 128 threads, tile 128(M)x64(N)x32(K), 4 warps stacked in M, warp tile 32x64.
// Grid: x = N-blocks (6, fastest) so CTAs sharing an A-tile are wave-adjacent
// and A re-reads hit L2 (~12.6 MB wave footprint vs 126 MB L2).
#define TBM 128
#define TBN 64
#define TBK 32
#define A_OPB 8192          // 128 rows * 64 B
#define W_OPB 4096          // 64 rows * 64 B
#define STAGEB (2*A_OPB + 2*W_OPB)   // 24 KB
#define SM_AHI 0
#define SM_ALO A_OPB
#define SM_WHI (2*A_OPB)
#define SM_WLO (2*A_OPB + W_OPB)
#define SMEM_GEMM (2*STAGEB)         // 48 KB

__global__ void __launch_bounds__(128, 4) gemm_bb(
    const __nv_bfloat16* __restrict__ Ahi, const __nv_bfloat16* __restrict__ Alo,
    const __nv_bfloat16* __restrict__ Whi, const __nv_bfloat16* __restrict__ Wlo,
    float* __restrict__ C, int M)
{
    extern __shared__ char sm[];
    const uint32_t sb = smem_u32(sm);
    const int tid = threadIdx.x;
    const int wid = tid >> 5, lid = tid & 31;
    const int warpM = wid;
    const int bm = blockIdx.y * TBM, bn = blockIdx.x * TBN;   // N fastest

    float acc[2][8][4];
    #pragma unroll
    for (int a = 0; a < 2; a++)
        #pragma unroll
        for (int b = 0; b < 8; b++)
            #pragma unroll
            for (int c = 0; c < 4; c++) acc[a][b][c] = 0.f;

    // cp.async indices
    const int arow = bm + tid;
    const int asz  = (arow < M) ? 16 : 0;
    const int arc  = (arow < M) ? arow : (M - 1);
    const char* Ah = (const char*)(Ahi + (size_t)arc * DIM);
    const char* Al = (const char*)(Alo + (size_t)arc * DIM);
    const char* Wh = (const char*)(Whi + (size_t)(bn + (tid >> 1)) * DIM);
    const char* Wl = (const char*)(Wlo + (size_t)(bn + (tid >> 1)) * DIM);
    const uint32_t wd0 = swz((uint32_t)(tid >> 1) * 64 + (tid & 1) * 32);
    const uint32_t wd1 = swz((uint32_t)(tid >> 1) * 64 + (tid & 1) * 32 + 16);

    auto stage_load = [&](int s, int kc) {
        uint32_t base = sb + s * STAGEB;
        const int go  = kc * 64;
        #pragma unroll
        for (int j = 0; j < 4; j++) {
            uint32_t ad = swz((uint32_t)tid * 64 + j * 16);
            cp16(base + SM_AHI + ad, Ah + go + j * 16, asz);
            cp16(base + SM_ALO + ad, Al + go + j * 16, asz);
        }
        const int wgo = go + (tid & 1) * 32;
        cp16(base + SM_WHI + wd0, Wh + wgo,      16);
        cp16(base + SM_WHI + wd1, Wh + wgo + 16, 16);
        cp16(base + SM_WLO + wd0, Wl + wgo,      16);
        cp16(base + SM_WLO + wd1, Wl + wgo + 16, 16);
        CP_COMMIT();
    };

    stage_load(0, 0);

    const int q  = lid >> 3;   // ldmatrix quadrant
    const int lq = lid & 7;

    #pragma unroll 1
    for (int kc = 0; kc < DIM / TBK; kc++) {
        CP_WAIT0();
        __syncthreads();
        if (kc < DIM / TBK - 1) stage_load((kc + 1) & 1, kc + 1);

        const uint32_t base = sb + (kc & 1) * STAGEB;

        #pragma unroll
        for (int ks = 0; ks < 2; ks++) {
            // hoist ALL fragment loads for this k-step before any MMA
            uint32_t bhf[4][4], blf[4][4];
            #pragma unroll
            for (int np = 0; np < 4; np++) {
                int r  = np * 16 + ((q >> 1) << 3) + lq;
                int kb = ks * 32 + ((q & 1) << 4);
                uint32_t off = swz((uint32_t)r * 64 + kb);
                LDSM4(bhf[np], base + SM_WHI + off);
                LDSM4(blf[np], base + SM_WLO + off);
            }
            uint32_t ahf[2][4], alf[2][4];
            #pragma unroll
            for (int mt = 0; mt < 2; mt++) {
                int r  = warpM * 32 + mt * 16 + ((q & 1) << 3) + lq;
                int kb = ks * 32 + ((q >> 1) << 4);
                uint32_t off = swz((uint32_t)r * 64 + kb);
                LDSM4(ahf[mt], base + SM_AHI + off);
                LDSM4(alf[mt], base + SM_ALO + off);
            }
            // MMAs: independent chains interleaved across np/mt/h
            #pragma unroll
            for (int np = 0; np < 4; np++) {
                #pragma unroll
                for (int mt = 0; mt < 2; mt++) {
                    #pragma unroll
                    for (int h = 0; h < 2; h++) {
                        int nt = np * 2 + h;
                        MMA_BF16(acc[mt][nt], ahf[mt], bhf[np][h*2], bhf[np][h*2+1]);
                        MMA_BF16(acc[mt][nt], ahf[mt], blf[np][h*2], blf[np][h*2+1]);
                        MMA_BF16(acc[mt][nt], alf[mt], bhf[np][h*2], bhf[np][h*2+1]);
                    }
                }
            }
        }
        // no bottom barrier — next iteration's top barrier provides WAR ordering
    }

    // epilogue: direct fp32 stores
    #pragma unroll
    for (int mt = 0; mt < 2; mt++) {
        int r0 = bm + warpM * 32 + mt * 16 + (lid >> 2);
        #pragma unroll
        for (int nt = 0; nt < 8; nt++) {
            int col = bn + nt * 8 + (lid & 3) * 2;
            if (r0 < M)
                *(float2*)(C + (size_t)r0 * GDIM + col) =
                    make_float2(acc[mt][nt][0], acc[mt][nt][1]);
            if (r0 + 8 < M)
                *(float2*)(C + (size_t)(r0 + 8) * GDIM + col) =
                    make_float2(acc[mt][nt][2], acc[mt][nt][3]);
        }
    }
}

// ---------------- elementwise kernels --------------------------------------
__global__ void split_k(const float* __restrict__ x,
                        __nv_bfloat16* __restrict__ hi,
                        __nv_bfloat16* __restrict__ lo, int n4)
{
    int i = blockIdx.x * blockDim.x + threadIdx.x;
    if (i >= n4) return;
    float4 v = ((const float4*)x)[i];
    split_store4(v, hi, lo, (size_t)i * 4);
}

__global__ void avg_k(const float* __restrict__ hs, float* __restrict__ h0,
                      __nv_bfloat16* __restrict__ h0hi, __nv_bfloat16* __restrict__ h0lo,
                      int m)
{
    int i = blockIdx.x * blockDim.x + threadIdx.x;
    int total = BSZ * m * (DIM / 4);
    if (i >= total) return;
    int dv = i & 63;
    int p  = i >> 6;
    int b = p / m, j = p - b * m;
    const float4* s0 = (const float4*)hs + ((size_t)(b * 2 * m + 2 * j)) * 64 + dv;
    float4 x = s0[0];
    float4 y = s0[64];
    float4 r = make_float4(0.5f*(x.x+y.x), 0.5f*(x.y+y.y),
                           0.5f*(x.z+y.z), 0.5f*(x.w+y.w));
    ((float4*)h0)[i] = r;
    split_store4(r, h0hi, h0lo, (size_t)i * 4);
}

__device__ __forceinline__ float sigmf(float x) { return 1.f / (1.f + __expf(-x)); }

__global__ void gates1_k(const float* __restrict__ GI, const float* __restrict__ GH,
                         const float* __restrict__ H0,
                         const float* __restrict__ b_ih, const float* __restrict__ b_hh,
                         float* __restrict__ h1,
                         __nv_bfloat16* __restrict__ h1hi, __nv_bfloat16* __restrict__ h1lo,
                         int m)
{
    int i = blockIdx.x * blockDim.x + threadIdx.x;
    int total = BSZ * m * DIM;
    if (i >= total) return;
    int d = i & 255;
    int p = i >> 8;
    int b = p / m, j = p - b * m;

    size_t gio = ((size_t)(b * 2 * m + 2 * j)) * GDIM;
    float gr = GI[gio + d]       + b_ih[d];
    float gz = GI[gio + 256 + d] + b_ih[256 + d];
    float gn = GI[gio + 512 + d] + b_ih[512 + d];

    float hr = b_hh[d], hz = b_hh[256 + d], hn = b_hh[512 + d];
    float h0v = 0.f;
    if (GH) {
        size_t gho = (size_t)p * GDIM;
        hr += GH[gho + d];
        hz += GH[gho + 256 + d];
        hn += GH[gho + 512 + d];
        h0v = H0[i];
    }
    float r  = sigmf(gr + hr);
    float z  = sigmf(gz + hz);
    float nn = tanhf(gn + r * hn);
    float v = (1.f - z) * nn + z * h0v;
    h1[i] = v;
    unsigned short hh, ll;
    split1(v, hh, ll);
    h1hi[i] = __ushort_as_bfloat16(hh);
    h1lo[i] = __ushort_as_bfloat16(ll);
}

__global__ void gates2_k(const float* __restrict__ GI, const float* __restrict__ GH,
                         const float* __restrict__ h1,
                         const float* __restrict__ b_ih, const float* __restrict__ b_hh,
                         float* __restrict__ emb_out, float* __restrict__ hs_out,
                         __nv_bfloat16* __restrict__ ehi, __nv_bfloat16* __restrict__ elo,
                         int m)
{
    int i = blockIdx.x * blockDim.x + threadIdx.x;
    int total = BSZ * m * DIM;
    if (i >= total) return;
    int d = i & 255;
    int p = i >> 8;
    int b = p / m, j = p - b * m;

    size_t gio = ((size_t)(b * 2 * m + 2 * j + 1)) * GDIM;
    float gr = GI[gio + d]       + b_ih[d];
    float gz = GI[gio + 256 + d] + b_ih[256 + d];
    float gn = GI[gio + 512 + d] + b_ih[512 + d];

    size_t gho = (size_t)p * GDIM;
    float hr = GH[gho + d]       + b_hh[d];
    float hz = GH[gho + 256 + d] + b_hh[256 + d];
    float hn = GH[gho + 512 + d] + b_hh[512 + d];

    float h1v = h1[i];
    float r  = sigmf(gr + hr);
    float z  = sigmf(gz + hz);
    float nn = tanhf(gn + r * hn);
    float h2 = (1.f - z) * nn + z * h1v;
    hs_out[i]  = h2;
    float ev = 0.5f * (h1v + h2);
    emb_out[i] = ev;
    unsigned short hh, ll;
    split1(ev, hh, ll);
    ehi[i] = __ushort_as_bfloat16(hh);
    elo[i] = __ushort_as_bfloat16(ll);
}

// ---------------- host orchestration ---------------------------------------
extern "C" void kernel_launch(void* const* d_in, const int* in_sizes, int n_in,
                              void* d_out, int out_size)
{
    const float* leaf = (const float*)d_in[0];
    const float* W_ih = (const float*)d_in[1];
    const float* W_hh = (const float*)d_in[2];
    const float* b_ih = (const float*)d_in[3];
    const float* b_hh = (const float*)d_in[4];
    float* out = (float*)d_out;

    float *p_emb, *p_hs, *p_h0, *p_h1, *p_GI, *p_GH;
    __nv_bfloat16 *p_lhi, *p_llo, *p_ehi, *p_elo;
    __nv_bfloat16 *p_h0hi, *p_h0lo, *p_h1hi, *p_h1lo;
    __nv_bfloat16 *p_wihhi, *p_wihlo, *p_whhhi, *p_whhlo;
    { void* p; cudaGetSymbolAddress(&p, g_emb);   p_emb   = (float*)p; }
    { void* p; cudaGetSymbolAddress(&p, g_hs);    p_hs    = (float*)p; }
    { void* p; cudaGetSymbolAddress(&p, g_h0);    p_h0    = (float*)p; }
    { void* p; cudaGetSymbolAddress(&p, g_h1);    p_h1    = (float*)p; }
    { void* p; cudaGetSymbolAddress(&p, g_GI);    p_GI    = (float*)p; }
    { void* p; cudaGetSymbolAddress(&p, g_GH);    p_GH    = (float*)p; }
    { void* p; cudaGetSymbolAddress(&p, g_lhi);   p_lhi   = (__nv_bfloat16*)p; }
    { void* p; cudaGetSymbolAddress(&p, g_llo);   p_llo   = (__nv_bfloat16*)p; }
    { void* p; cudaGetSymbolAddress(&p, g_ehi);   p_ehi   = (__nv_bfloat16*)p; }
    { void* p; cudaGetSymbolAddress(&p, g_elo);   p_elo   = (__nv_bfloat16*)p; }
    { void* p; cudaGetSymbolAddress(&p, g_h0hi);  p_h0hi  = (__nv_bfloat16*)p; }
    { void* p; cudaGetSymbolAddress(&p, g_h0lo);  p_h0lo  = (__nv_bfloat16*)p; }
    { void* p; cudaGetSymbolAddress(&p, g_h1hi);  p_h1hi  = (__nv_bfloat16*)p; }
    { void* p; cudaGetSymbolAddress(&p, g_h1lo);  p_h1lo  = (__nv_bfloat16*)p; }
    { void* p; cudaGetSymbolAddress(&p, g_wihhi); p_wihhi = (__nv_bfloat16*)p; }
    { void* p; cudaGetSymbolAddress(&p, g_wihlo); p_wihlo = (__nv_bfloat16*)p; }
    { void* p; cudaGetSymbolAddress(&p, g_whhhi); p_whhhi = (__nv_bfloat16*)p; }
    { void* p; cudaGetSymbolAddress(&p, g_whhlo); p_whhlo = (__nv_bfloat16*)p; }

    cudaFuncSetAttribute(gemm_bb, cudaFuncAttributeMaxDynamicSharedMemorySize,
                         SMEM_GEMM);

    // pre-split weights + leaf
    {
        int n4 = GDIM * DIM / 4;
        split_k<<<(n4 + 255) / 256, 256>>>(W_ih, p_wihhi, p_wihlo, n4);
        split_k<<<(n4 + 255) / 256, 256>>>(W_hh, p_whhhi, p_whhlo, n4);
        int l4 = BSZ * LSEQ * DIM / 4;
        split_k<<<(l4 + 255) / 256, 256>>>(leaf, p_lhi, p_llo, l4);
    }

    int n = LSEQ;
    bool have_hs = false;

    while (n > 1) {
        const int m   = n / 2;
        const int Mgi = BSZ * n;
        const int Mh  = BSZ * m;
        const int tot  = Mh * DIM;
        const int tot4 = tot / 4;

        const __nv_bfloat16* ahi = have_hs ? p_ehi : p_lhi;
        const __nv_bfloat16* alo = have_hs ? p_elo : p_llo;

        {   // GI = embeds @ W_ih^T
            dim3 grid(GDIM / TBN, (Mgi + TBM - 1) / TBM);
            gemm_bb<<<grid, 128, SMEM_GEMM>>>(ahi, alo, p_wihhi, p_wihlo, p_GI, Mgi);
        }

        if (have_hs) {
            avg_k<<<(tot4 + 255) / 256, 256>>>(p_hs, p_h0, p_h0hi, p_h0lo, m);
            dim3 grid(GDIM / TBN, (Mh + TBM - 1) / TBM);
            gemm_bb<<<grid, 128, SMEM_GEMM>>>(p_h0hi, p_h0lo, p_whhhi, p_whhlo, p_GH, Mh);
        }

        gates1_k<<<(tot + 255) / 256, 256>>>(
            p_GI, have_hs ? p_GH : nullptr, have_hs ? p_h0 : nullptr,
            b_ih, b_hh, p_h1, p_h1hi, p_h1lo, m);

        {
            dim3 grid(GDIM / TBN, (Mh + TBM - 1) / TBM);
            gemm_bb<<<grid, 128, SMEM_GEMM>>>(p_h1hi, p_h1lo, p_whhhi, p_whhlo, p_GH, Mh);
        }

        float* emb_out = (m == 1) ? out : p_emb;
        gates2_k<<<(tot + 255) / 256, 256>>>(
            p_GI, p_GH, p_h1, b_ih, b_hh, emb_out, p_hs, p_ehi, p_elo, m);

        have_hs = true;
        n = m;
    }
}

// round 7
// speedup vs baseline: 1.4661x; 1.4661x over previous
#include <cuda_runtime.h>
#include <cuda_bf16.h>
#include <cstdint>
#include <math.h>

// Problem constants
#define BSZ 32
#define LSEQ 4096
#define DIM 256
#define GDIM 768   // 3*DIM

// ---------------- scratch (device globals; no allocation allowed) ----------
__device__ float g_emb[BSZ * (LSEQ/2) * DIM];
__device__ float g_hs [BSZ * (LSEQ/2) * DIM];
__device__ float g_h0 [BSZ * (LSEQ/2) * DIM];
__device__ float g_h1 [BSZ * (LSEQ/2) * DIM];
__device__ float g_GI [(size_t)BSZ * LSEQ * GDIM];
__device__ float g_GH [(size_t)BSZ * (LSEQ/2) * GDIM];

// bf16 split operand buffers
__device__ __nv_bfloat16 g_lhi[(size_t)BSZ * LSEQ * DIM];
__device__ __nv_bfloat16 g_llo[(size_t)BSZ * LSEQ * DIM];
__device__ __nv_bfloat16 g_ehi[(size_t)BSZ * (LSEQ/2) * DIM];
__device__ __nv_bfloat16 g_elo[(size_t)BSZ * (LSEQ/2) * DIM];
__device__ __nv_bfloat16 g_h0hi[(size_t)BSZ * (LSEQ/2) * DIM];
__device__ __nv_bfloat16 g_h0lo[(size_t)BSZ * (LSEQ/2) * DIM];
__device__ __nv_bfloat16 g_h1hi[(size_t)BSZ * (LSEQ/2) * DIM];
__device__ __nv_bfloat16 g_h1lo[(size_t)BSZ * (LSEQ/2) * DIM];
__device__ __nv_bfloat16 g_wihhi[GDIM * DIM], g_wihlo[GDIM * DIM];
__device__ __nv_bfloat16 g_whhhi[GDIM * DIM], g_whhlo[GDIM * DIM];

// ======================= helpers ==========================
__device__ __forceinline__ uint32_t smem_u32(const void* p) {
    uint32_t a;
    asm("{ .reg .u64 t; cvta.to.shared.u64 t, %1; cvt.u32.u64 %0, t; }"
        : "=r"(a) : "l"(p));
    return a;
}

__device__ __forceinline__ uint32_t swz(uint32_t b) { return b ^ ((b >> 3) & 0x70); }

__device__ __forceinline__ void cp16(uint32_t dst, const void* src, int sz) {
    asm volatile("cp.async.cg.shared.global [%0], [%1], 16, %2;"
                 :: "r"(dst), "l"(src), "r"(sz));
}

#define CP_COMMIT() asm volatile("cp.async.commit_group;" ::: "memory")
#define CP_WAIT0()  asm volatile("cp.async.wait_group 0;" ::: "memory")
#define CP_WAIT1()  asm volatile("cp.async.wait_group 1;" ::: "memory")

#define LDSM4(R, addr) \
    asm volatile("ldmatrix.sync.aligned.m8n8.x4.shared.b16 {%0,%1,%2,%3}, [%4];" \
        : "=r"((R)[0]), "=r"((R)[1]), "=r"((R)[2]), "=r"((R)[3]) : "r"(addr))

#define MMA_BF16(C, A, B0, B1) \
    asm volatile("mma.sync.aligned.m16n8k16.row.col.f32.bf16.bf16.f32 " \
        "{%0,%1,%2,%3},{%4,%5,%6,%7},{%8,%9},{%0,%1,%2,%3};" \
        : "+f"((C)[0]), "+f"((C)[1]), "+f"((C)[2]), "+f"((C)[3]) \
        : "r"((A)[0]), "r"((A)[1]), "r"((A)[2]), "r"((A)[3]), "r"(B0), "r"(B1))

__device__ __forceinline__ void split1(float x, unsigned short& h, unsigned short& l) {
    __nv_bfloat16 hb = __float2bfloat16(x);
    float resid = x - __bfloat162float(hb);
    __nv_bfloat16 lb = __float2bfloat16(resid);
    h = __bfloat16_as_ushort(hb);
    l = __bfloat16_as_ushort(lb);
}

__device__ __forceinline__ void split_store4(float4 v,
    __nv_bfloat16* __restrict__ hi, __nv_bfloat16* __restrict__ lo, size_t idx)
{
    unsigned short h[4], l[4];
    split1(v.x, h[0], l[0]); split1(v.y, h[1], l[1]);
    split1(v.z, h[2], l[2]); split1(v.w, h[3], l[3]);
    uint2 hv = make_uint2((uint32_t)h[0] | ((uint32_t)h[1] << 16),
                          (uint32_t)h[2] | ((uint32_t)h[3] << 16));
    uint2 lv = make_uint2((uint32_t)l[0] | ((uint32_t)l[1] << 16),
                          (uint32_t)l[2] | ((uint32_t)l[3] << 16));
    *(uint2*)(hi + idx) = hv;
    *(uint2*)(lo + idx) = lv;
}

// ======================= tensor-core GEMM (mma.sync bf16 split) =============
// C[M,768] = A[M,256] @ W[768,256]^T,  A/W pre-split bf16 hi/lo.
// 128 threads, tile 128(M)x64(N)x32(K), 4 warps stacked in M, warp tile 32x64.
// 3-stage cp.async ring (prefetch 2 chunks ahead), 3 CTAs/SM.
// Grid: M-block fastest (blockIdx.x) — keeps DRAM streams diverse (R6 lesson).
#define TBM 128
#define TBN 64
#define TBK 32
#define NCH (DIM/TBK)       // 8 k-chunks
#define A_OPB 8192          // 128 rows * 64 B
#define W_OPB 4096          // 64 rows * 64 B
#define STAGEB (2*A_OPB + 2*W_OPB)   // 24 KB
#define SM_AHI 0
#define SM_ALO A_OPB
#define SM_WHI (2*A_OPB)
#define SM_WLO (2*A_OPB + W_OPB)
#define SMEM_GEMM (3*STAGEB)         // 72 KB, 3 stages

__global__ void __launch_bounds__(128, 3) gemm_bb(
    const __nv_bfloat16* __restrict__ Ahi, const __nv_bfloat16* __restrict__ Alo,
    const __nv_bfloat16* __restrict__ Whi, const __nv_bfloat16* __restrict__ Wlo,
    float* __restrict__ C, int M)
{
    extern __shared__ char sm[];
    const uint32_t sb = smem_u32(sm);
    const int tid = threadIdx.x;
    const int wid = tid >> 5, lid = tid & 31;
    const int warpM = wid;
    const int bm = blockIdx.x * TBM, bn = blockIdx.y * TBN;   // M fastest

    float acc[2][8][4];
    #pragma unroll
    for (int a = 0; a < 2; a++)
        #pragma unroll
        for (int b = 0; b < 8; b++)
            #pragma unroll
            for (int c = 0; c < 4; c++) acc[a][b][c] = 0.f;

    // cp.async indices
    const int arow = bm + tid;
    const int asz  = (arow < M) ? 16 : 0;
    const int arc  = (arow < M) ? arow : (M - 1);
    const char* Ah = (const char*)(Ahi + (size_t)arc * DIM);
    const char* Al = (const char*)(Alo + (size_t)arc * DIM);
    const char* Wh = (const char*)(Whi + (size_t)(bn + (tid >> 1)) * DIM);
    const char* Wl = (const char*)(Wlo + (size_t)(bn + (tid >> 1)) * DIM);
    const uint32_t wd0 = swz((uint32_t)(tid >> 1) * 64 + (tid & 1) * 32);
    const uint32_t wd1 = swz((uint32_t)(tid >> 1) * 64 + (tid & 1) * 32 + 16);

    auto stage_load = [&](int s, int kc) {
        uint32_t base = sb + s * STAGEB;
        const int go  = kc * 64;
        #pragma unroll
        for (int j = 0; j < 4; j++) {
            uint32_t ad = swz((uint32_t)tid * 64 + j * 16);
            cp16(base + SM_AHI + ad, Ah + go + j * 16, asz);
            cp16(base + SM_ALO + ad, Al + go + j * 16, asz);
        }
        const int wgo = go + (tid & 1) * 32;
        cp16(base + SM_WHI + wd0, Wh + wgo,      16);
        cp16(base + SM_WHI + wd1, Wh + wgo + 16, 16);
        cp16(base + SM_WLO + wd0, Wl + wgo,      16);
        cp16(base + SM_WLO + wd1, Wl + wgo + 16, 16);
        CP_COMMIT();
    };

    // prologue: 2 chunks in flight
    stage_load(0, 0);
    stage_load(1, 1);

    const int q  = lid >> 3;   // ldmatrix quadrant
    const int lq = lid & 7;

    #pragma unroll 1
    for (int kc = 0; kc < NCH; kc++) {
        // steady state: oldest of <=2 pending groups is chunk kc
        if (kc + 1 < NCH) CP_WAIT1(); else CP_WAIT0();
        __syncthreads();
        // stage (kc+2)%3 was last read at iter kc-1; barrier above makes it free
        if (kc + 2 < NCH) stage_load((kc + 2) % 3, kc + 2);

        const uint32_t base = sb + (kc % 3) * STAGEB;

        #pragma unroll
        for (int ks = 0; ks < 2; ks++) {
            // hoist ALL fragment loads for this k-step before any MMA
            uint32_t bhf[4][4], blf[4][4];
            #pragma unroll
            for (int np = 0; np < 4; np++) {
                int r  = np * 16 + ((q >> 1) << 3) + lq;
                int kb = ks * 32 + ((q & 1) << 4);
                uint32_t off = swz((uint32_t)r * 64 + kb);
                LDSM4(bhf[np], base + SM_WHI + off);
                LDSM4(blf[np], base + SM_WLO + off);
            }
            uint32_t ahf[2][4], alf[2][4];
            #pragma unroll
            for (int mt = 0; mt < 2; mt++) {
                int r  = warpM * 32 + mt * 16 + ((q & 1) << 3) + lq;
                int kb = ks * 32 + ((q >> 1) << 4);
                uint32_t off = swz((uint32_t)r * 64 + kb);
                LDSM4(ahf[mt], base + SM_AHI + off);
                LDSM4(alf[mt], base + SM_ALO + off);
            }
            // MMAs: independent chains interleaved across np/mt/h
            #pragma unroll
            for (int np = 0; np < 4; np++) {
                #pragma unroll
                for (int mt = 0; mt < 2; mt++) {
                    #pragma unroll
                    for (int h = 0; h < 2; h++) {
                        int nt = np * 2 + h;
                        MMA_BF16(acc[mt][nt], ahf[mt], bhf[np][h*2], bhf[np][h*2+1]);
                        MMA_BF16(acc[mt][nt], ahf[mt], blf[np][h*2], blf[np][h*2+1]);
                        MMA_BF16(acc[mt][nt], alf[mt], bhf[np][h*2], bhf[np][h*2+1]);
                    }
                }
            }
        }
        // no bottom barrier — next iteration's top barrier provides WAR ordering
    }

    // epilogue: direct fp32 stores
    #pragma unroll
    for (int mt = 0; mt < 2; mt++) {
        int r0 = bm + warpM * 32 + mt * 16 + (lid >> 2);
        #pragma unroll
        for (int nt = 0; nt < 8; nt++) {
            int col = bn + nt * 8 + (lid & 3) * 2;
            if (r0 < M)
                *(float2*)(C + (size_t)r0 * GDIM + col) =
                    make_float2(acc[mt][nt][0], acc[mt][nt][1]);
            if (r0 + 8 < M)
                *(float2*)(C + (size_t)(r0 + 8) * GDIM + col) =
                    make_float2(acc[mt][nt][2], acc[mt][nt][3]);
        }
    }
}

// ---------------- elementwise kernels --------------------------------------
__global__ void split_k(const float* __restrict__ x,
                        __nv_bfloat16* __restrict__ hi,
                        __nv_bfloat16* __restrict__ lo, int n4)
{
    int i = blockIdx.x * blockDim.x + threadIdx.x;
    if (i >= n4) return;
    float4 v = ((const float4*)x)[i];
    split_store4(v, hi, lo, (size_t)i * 4);
}

__global__ void avg_k(const float* __restrict__ hs, float* __restrict__ h0,
                      __nv_bfloat16* __restrict__ h0hi, __nv_bfloat16* __restrict__ h0lo,
                      int m)
{
    int i = blockIdx.x * blockDim.x + threadIdx.x;
    int total = BSZ * m * (DIM / 4);
    if (i >= total) return;
    int dv = i & 63;
    int p  = i >> 6;
    int b = p / m, j = p - b * m;
    const float4* s0 = (const float4*)hs + ((size_t)(b * 2 * m + 2 * j)) * 64 + dv;
    float4 x = s0[0];
    float4 y = s0[64];
    float4 r = make_float4(0.5f*(x.x+y.x), 0.5f*(x.y+y.y),
                           0.5f*(x.z+y.z), 0.5f*(x.w+y.w));
    ((float4*)h0)[i] = r;
    split_store4(r, h0hi, h0lo, (size_t)i * 4);
}

__device__ __forceinline__ float sigmf(float x) { return 1.f / (1.f + __expf(-x)); }

__global__ void gates1_k(const float* __restrict__ GI, const float* __restrict__ GH,
                         const float* __restrict__ H0,
                         const float* __restrict__ b_ih, const float* __restrict__ b_hh,
                         float* __restrict__ h1,
                         __nv_bfloat16* __restrict__ h1hi, __nv_bfloat16* __restrict__ h1lo,
                         int m)
{
    int i = blockIdx.x * blockDim.x + threadIdx.x;
    int total = BSZ * m * DIM;
    if (i >= total) return;
    int d = i & 255;
    int p = i >> 8;
    int b = p / m, j = p - b * m;

    size_t gio = ((size_t)(b * 2 * m + 2 * j)) * GDIM;
    float gr = GI[gio + d]       + b_ih[d];
    float gz = GI[gio + 256 + d] + b_ih[256 + d];
    float gn = GI[gio + 512 + d] + b_ih[512 + d];

    float hr = b_hh[d], hz = b_hh[256 + d], hn = b_hh[512 + d];
    float h0v = 0.f;
    if (GH) {
        size_t gho = (size_t)p * GDIM;
        hr += GH[gho + d];
        hz += GH[gho + 256 + d];
        hn += GH[gho + 512 + d];
        h0v = H0[i];
    }
    float r  = sigmf(gr + hr);
    float z  = sigmf(gz + hz);
    float nn = tanhf(gn + r * hn);
    float v = (1.f - z) * nn + z * h0v;
    h1[i] = v;
    unsigned short hh, ll;
    split1(v, hh, ll);
    h1hi[i] = __ushort_as_bfloat16(hh);
    h1lo[i] = __ushort_as_bfloat16(ll);
}

__global__ void gates2_k(const float* __restrict__ GI, const float* __restrict__ GH,
                         const float* __restrict__ h1,
                         const float* __restrict__ b_ih, const float* __restrict__ b_hh,
                         float* __restrict__ emb_out, float* __restrict__ hs_out,
                         __nv_bfloat16* __restrict__ ehi, __nv_bfloat16* __restrict__ elo,
                         int m)
{
    int i = blockIdx.x * blockDim.x + threadIdx.x;
    int total = BSZ * m * DIM;
    if (i >= total) return;
    int d = i & 255;
    int p = i >> 8;
    int b = p / m, j = p - b * m;

    size_t gio = ((size_t)(b * 2 * m + 2 * j + 1)) * GDIM;
    float gr = GI[gio + d]       + b_ih[d];
    float gz = GI[gio + 256 + d] + b_ih[256 + d];
    float gn = GI[gio + 512 + d] + b_ih[512 + d];

    size_t gho = (size_t)p * GDIM;
    float hr = GH[gho + d]       + b_hh[d];
    float hz = GH[gho + 256 + d] + b_hh[256 + d];
    float hn = GH[gho + 512 + d] + b_hh[512 + d];

    float h1v = h1[i];
    float r  = sigmf(gr + hr);
    float z  = sigmf(gz + hz);
    float nn = tanhf(gn + r * hn);
    float h2 = (1.f - z) * nn + z * h1v;
    hs_out[i]  = h2;
    float ev = 0.5f * (h1v + h2);
    emb_out[i] = ev;
    unsigned short hh, ll;
    split1(ev, hh, ll);
    ehi[i] = __ushort_as_bfloat16(hh);
    elo[i] = __ushort_as_bfloat16(ll);
}

// ---------------- host orchestration ---------------------------------------
extern "C" void kernel_launch(void* const* d_in, const int* in_sizes, int n_in,
                              void* d_out, int out_size)
{
    const float* leaf = (const float*)d_in[0];
    const float* W_ih = (const float*)d_in[1];
    const float* W_hh = (const float*)d_in[2];
    const float* b_ih = (const float*)d_in[3];
    const float* b_hh = (const float*)d_in[4];
    float* out = (float*)d_out;

    float *p_emb, *p_hs, *p_h0, *p_h1, *p_GI, *p_GH;
    __nv_bfloat16 *p_lhi, *p_llo, *p_ehi, *p_elo;
    __nv_bfloat16 *p_h0hi, *p_h0lo, *p_h1hi, *p_h1lo;
    __nv_bfloat16 *p_wihhi, *p_wihlo, *p_whhhi, *p_whhlo;
    { void* p; cudaGetSymbolAddress(&p, g_emb);   p_emb   = (float*)p; }
    { void* p; cudaGetSymbolAddress(&p, g_hs);    p_hs    = (float*)p; }
    { void* p; cudaGetSymbolAddress(&p, g_h0);    p_h0    = (float*)p; }
    { void* p; cudaGetSymbolAddress(&p, g_h1);    p_h1    = (float*)p; }
    { void* p; cudaGetSymbolAddress(&p, g_GI);    p_GI    = (float*)p; }
    { void* p; cudaGetSymbolAddress(&p, g_GH);    p_GH    = (float*)p; }
    { void* p; cudaGetSymbolAddress(&p, g_lhi);   p_lhi   = (__nv_bfloat16*)p; }
    { void* p; cudaGetSymbolAddress(&p, g_llo);   p_llo   = (__nv_bfloat16*)p; }
    { void* p; cudaGetSymbolAddress(&p, g_ehi);   p_ehi   = (__nv_bfloat16*)p; }
    { void* p; cudaGetSymbolAddress(&p, g_elo);   p_elo   = (__nv_bfloat16*)p; }
    { void* p; cudaGetSymbolAddress(&p, g_h0hi);  p_h0hi  = (__nv_bfloat16*)p; }
    { void* p; cudaGetSymbolAddress(&p, g_h0lo);  p_h0lo  = (__nv_bfloat16*)p; }
    { void* p; cudaGetSymbolAddress(&p, g_h1hi);  p_h1hi  = (__nv_bfloat16*)p; }
    { void* p; cudaGetSymbolAddress(&p, g_h1lo);  p_h1lo  = (__nv_bfloat16*)p; }
    { void* p; cudaGetSymbolAddress(&p, g_wihhi); p_wihhi = (__nv_bfloat16*)p; }
    { void* p; cudaGetSymbolAddress(&p, g_wihlo); p_wihlo = (__nv_bfloat16*)p; }
    { void* p; cudaGetSymbolAddress(&p, g_whhhi); p_whhhi = (__nv_bfloat16*)p; }
    { void* p; cudaGetSymbolAddress(&p, g_whhlo); p_whhlo = (__nv_bfloat16*)p; }

    cudaFuncSetAttribute(gemm_bb, cudaFuncAttributeMaxDynamicSharedMemorySize,
                         SMEM_GEMM);

    // pre-split weights + leaf
    {
        int n4 = GDIM * DIM / 4;
        split_k<<<(n4 + 255) / 256, 256>>>(W_ih, p_wihhi, p_wihlo, n4);
        split_k<<<(n4 + 255) / 256, 256>>>(W_hh, p_whhhi, p_whhlo, n4);
        int l4 = BSZ * LSEQ * DIM / 4;
        split_k<<<(l4 + 255) / 256, 256>>>(leaf, p_lhi, p_llo, l4);
    }

    int n = LSEQ;
    bool have_hs = false;

    while (n > 1) {
        const int m   = n / 2;
        const int Mgi = BSZ * n;
        const int Mh  = BSZ * m;
        const int tot  = Mh * DIM;
        const int tot4 = tot / 4;

        const __nv_bfloat16* ahi = have_hs ? p_ehi : p_lhi;
        const __nv_bfloat16* alo = have_hs ? p_elo : p_llo;

        {   // GI = embeds @ W_ih^T
            dim3 grid((Mgi + TBM - 1) / TBM, GDIM / TBN);
            gemm_bb<<<grid, 128, SMEM_GEMM>>>(ahi, alo, p_wihhi, p_wihlo, p_GI, Mgi);
        }

        if (have_hs) {
            avg_k<<<(tot4 + 255) / 256, 256>>>(p_hs, p_h0, p_h0hi, p_h0lo, m);
            dim3 grid((Mh + TBM - 1) / TBM, GDIM / TBN);
            gemm_bb<<<grid, 128, SMEM_GEMM>>>(p_h0hi, p_h0lo, p_whhhi, p_whhlo, p_GH, Mh);
        }

        gates1_k<<<(tot + 255) / 256, 256>>>(
            p_GI, have_hs ? p_GH : nullptr, have_hs ? p_h0 : nullptr,
            b_ih, b_hh, p_h1, p_h1hi, p_h1lo, m);

        {
            dim3 grid((Mh + TBM - 1) / TBM, GDIM / TBN);
            gemm_bb<<<grid, 128, SMEM_GEMM>>>(p_h1hi, p_h1lo, p_whhhi, p_whhlo, p_GH, Mh);
        }

        float* emb_out = (m == 1) ? out : p_emb;
        gates2_k<<<(tot + 255) / 256, 256>>>(
            p_GI, p_GH, p_h1, b_ih, b_hh, emb_out, p_hs, p_ehi, p_elo, m);

        have_hs = true;
        n = m;
    }
}

// round 8
// speedup vs baseline: 2.5296x; 1.7254x over previous
#include <cuda_runtime.h>
#include <cuda_fp16.h>
#include <cstdint>
#include <math.h>

// Problem constants
#define BSZ 32
#define LSEQ 4096
#define DIM 256
#define GDIM 768   // 3*DIM

// ---------------- scratch (device globals; no allocation allowed) ----------
__device__ float g_hs [BSZ * (LSEQ/2) * DIM];
__device__ float g_h0 [BSZ * (LSEQ/2) * DIM];
__device__ float g_h1 [BSZ * (LSEQ/2) * DIM];
__device__ float g_GI [(size_t)BSZ * LSEQ * GDIM];
__device__ float g_GH [(size_t)BSZ * (LSEQ/2) * GDIM];

// fp16 operand buffers
__device__ __half g_lh  [(size_t)BSZ * LSEQ * DIM];      // leaf fp16
__device__ __half g_eh  [(size_t)BSZ * (LSEQ/2) * DIM];  // emb fp16
__device__ __half g_h0h [(size_t)BSZ * (LSEQ/2) * DIM];
__device__ __half g_h1h [(size_t)BSZ * (LSEQ/2) * DIM];
__device__ __half g_wihh[GDIM * DIM];
__device__ __half g_whhh[GDIM * DIM];

// ======================= helpers ==========================
__device__ __forceinline__ uint32_t smem_u32(const void* p) {
    uint32_t a;
    asm("{ .reg .u64 t; cvta.to.shared.u64 t, %1; cvt.u32.u64 %0, t; }"
        : "=r"(a) : "l"(p));
    return a;
}

__device__ __forceinline__ uint32_t swz(uint32_t b) { return b ^ ((b >> 3) & 0x70); }

__device__ __forceinline__ void cp16(uint32_t dst, const void* src, int sz) {
    asm volatile("cp.async.cg.shared.global [%0], [%1], 16, %2;"
                 :: "r"(dst), "l"(src), "r"(sz));
}

#define CP_COMMIT() asm volatile("cp.async.commit_group;" ::: "memory")
#define CP_WAIT0()  asm volatile("cp.async.wait_group 0;" ::: "memory")
#define CP_WAIT1()  asm volatile("cp.async.wait_group 1;" ::: "memory")

#define LDSM4(R, addr) \
    asm volatile("ldmatrix.sync.aligned.m8n8.x4.shared.b16 {%0,%1,%2,%3}, [%4];" \
        : "=r"((R)[0]), "=r"((R)[1]), "=r"((R)[2]), "=r"((R)[3]) : "r"(addr))

#define MMA_F16(C, A, B0, B1) \
    asm volatile("mma.sync.aligned.m16n8k16.row.col.f32.f16.f16.f32 " \
        "{%0,%1,%2,%3},{%4,%5,%6,%7},{%8,%9},{%0,%1,%2,%3};" \
        : "+f"((C)[0]), "+f"((C)[1]), "+f"((C)[2]), "+f"((C)[3]) \
        : "r"((A)[0]), "r"((A)[1]), "r"((A)[2]), "r"((A)[3]), "r"(B0), "r"(B1))

__device__ __forceinline__ void h4_store(float4 v, __half* __restrict__ dst, size_t idx) {
    __half2 lo = __floats2half2_rn(v.x, v.y);
    __half2 hi = __floats2half2_rn(v.z, v.w);
    *(uint2*)(dst + idx) = make_uint2(*(uint32_t*)&lo, *(uint32_t*)&hi);
}

// ======================= tensor-core GEMM (mma.sync fp16) ===================
// C[M,768] = A[M,256] @ W[768,256]^T,  A/W fp16, fp32 accum.
// 128 threads, tile 128(M)x64(N)x32(K), 4 warps stacked in M, warp tile 32x64.
// 3-stage cp.async ring, 4 CTAs/SM. Grid: M-block fastest.
#define TBM 128
#define TBN 64
#define TBK 32
#define NCH (DIM/TBK)       // 8 k-chunks
#define A_OPB 8192          // 128 rows * 64 B
#define W_OPB 4096          // 64 rows * 64 B
#define STAGEB (A_OPB + W_OPB)   // 12 KB
#define SM_A 0
#define SM_W A_OPB
#define SMEM_GEMM (3*STAGEB)     // 36 KB

__global__ void __launch_bounds__(128, 4) gemm_f16(
    const __half* __restrict__ A, const __half* __restrict__ W,
    float* __restrict__ C, int M)
{
    extern __shared__ char sm[];
    const uint32_t sb = smem_u32(sm);
    const int tid = threadIdx.x;
    const int wid = tid >> 5, lid = tid & 31;
    const int warpM = wid;
    const int bm = blockIdx.x * TBM, bn = blockIdx.y * TBN;   // M fastest

    float acc[2][8][4];
    #pragma unroll
    for (int a = 0; a < 2; a++)
        #pragma unroll
        for (int b = 0; b < 8; b++)
            #pragma unroll
            for (int c = 0; c < 4; c++) acc[a][b][c] = 0.f;

    // cp.async indices: A: 1 thread per row (4x16B); W: 2 threads per row (2x16B)
    const int arow = bm + tid;
    const int asz  = (arow < M) ? 16 : 0;
    const int arc  = (arow < M) ? arow : (M - 1);
    const char* Ap = (const char*)(A + (size_t)arc * DIM);
    const char* Wp = (const char*)(W + (size_t)(bn + (tid >> 1)) * DIM);
    const uint32_t wd0 = swz((uint32_t)(tid >> 1) * 64 + (tid & 1) * 32);
    const uint32_t wd1 = swz((uint32_t)(tid >> 1) * 64 + (tid & 1) * 32 + 16);

    auto stage_load = [&](int s, int kc) {
        uint32_t base = sb + s * STAGEB;
        const int go  = kc * 64;
        #pragma unroll
        for (int j = 0; j < 4; j++) {
            uint32_t ad = swz((uint32_t)tid * 64 + j * 16);
            cp16(base + SM_A + ad, Ap + go + j * 16, asz);
        }
        const int wgo = go + (tid & 1) * 32;
        cp16(base + SM_W + wd0, Wp + wgo,      16);
        cp16(base + SM_W + wd1, Wp + wgo + 16, 16);
        CP_COMMIT();
    };

    // prologue: 2 chunks in flight
    stage_load(0, 0);
    stage_load(1, 1);

    const int q  = lid >> 3;   // ldmatrix quadrant
    const int lq = lid & 7;

    #pragma unroll 1
    for (int kc = 0; kc < NCH; kc++) {
        if (kc + 1 < NCH) CP_WAIT1(); else CP_WAIT0();
        __syncthreads();
        if (kc + 2 < NCH) stage_load((kc + 2) % 3, kc + 2);

        const uint32_t base = sb + (kc % 3) * STAGEB;

        #pragma unroll
        for (int ks = 0; ks < 2; ks++) {
            // hoist all fragment loads before MMAs
            uint32_t bf[4][4];
            #pragma unroll
            for (int np = 0; np < 4; np++) {
                int r  = np * 16 + ((q >> 1) << 3) + lq;
                int kb = ks * 32 + ((q & 1) << 4);
                uint32_t off = swz((uint32_t)r * 64 + kb);
                LDSM4(bf[np], base + SM_W + off);
            }
            uint32_t af[2][4];
            #pragma unroll
            for (int mt = 0; mt < 2; mt++) {
                int r  = warpM * 32 + mt * 16 + ((q & 1) << 3) + lq;
                int kb = ks * 32 + ((q >> 1) << 4);
                uint32_t off = swz((uint32_t)r * 64 + kb);
                LDSM4(af[mt], base + SM_A + off);
            }
            #pragma unroll
            for (int np = 0; np < 4; np++) {
                #pragma unroll
                for (int mt = 0; mt < 2; mt++) {
                    #pragma unroll
                    for (int h = 0; h < 2; h++) {
                        MMA_F16(acc[mt][np*2+h], af[mt], bf[np][h*2], bf[np][h*2+1]);
                    }
                }
            }
        }
        // no bottom barrier — next iteration's top barrier provides WAR ordering
    }

    // epilogue: direct fp32 stores
    #pragma unroll
    for (int mt = 0; mt < 2; mt++) {
        int r0 = bm + warpM * 32 + mt * 16 + (lid >> 2);
        #pragma unroll
        for (int nt = 0; nt < 8; nt++) {
            int col = bn + nt * 8 + (lid & 3) * 2;
            if (r0 < M)
                *(float2*)(C + (size_t)r0 * GDIM + col) =
                    make_float2(acc[mt][nt][0], acc[mt][nt][1]);
            if (r0 + 8 < M)
                *(float2*)(C + (size_t)(r0 + 8) * GDIM + col) =
                    make_float2(acc[mt][nt][2], acc[mt][nt][3]);
        }
    }
}

// ---------------- elementwise kernels --------------------------------------
// fp32 -> fp16 converter
__global__ void cvt_k(const float* __restrict__ x, __half* __restrict__ h, int n4)
{
    int i = blockIdx.x * blockDim.x + threadIdx.x;
    if (i >= n4) return;
    float4 v = ((const float4*)x)[i];
    h4_store(v, h, (size_t)i * 4);
}

// H0 = 0.5*(hs even + hs odd), fp32 + fp16
__global__ void avg_k(const float* __restrict__ hs, float* __restrict__ h0,
                      __half* __restrict__ h0h, int m)
{
    int i = blockIdx.x * blockDim.x + threadIdx.x;
    int total = BSZ * m * (DIM / 4);
    if (i >= total) return;
    int dv = i & 63;
    int p  = i >> 6;
    int b = p / m, j = p - b * m;
    const float4* s0 = (const float4*)hs + ((size_t)(b * 2 * m + 2 * j)) * 64 + dv;
    float4 x = s0[0];
    float4 y = s0[64];
    float4 r = make_float4(0.5f*(x.x+y.x), 0.5f*(x.y+y.y),
                           0.5f*(x.z+y.z), 0.5f*(x.w+y.w));
    ((float4*)h0)[i] = r;
    h4_store(r, h0h, (size_t)i * 4);
}

__device__ __forceinline__ float sigmf(float x) { return 1.f / (1.f + __expf(-x)); }

__global__ void gates1_k(const float* __restrict__ GI, const float* __restrict__ GH,
                         const float* __restrict__ H0,
                         const float* __restrict__ b_ih, const float* __restrict__ b_hh,
                         float* __restrict__ h1, __half* __restrict__ h1h, int m)
{
    int i = blockIdx.x * blockDim.x + threadIdx.x;
    int total = BSZ * m * DIM;
    if (i >= total) return;
    int d = i & 255;
    int p = i >> 8;
    int b = p / m, j = p - b * m;

    size_t gio = ((size_t)(b * 2 * m + 2 * j)) * GDIM;
    float gr = GI[gio + d]       + b_ih[d];
    float gz = GI[gio + 256 + d] + b_ih[256 + d];
    float gn = GI[gio + 512 + d] + b_ih[512 + d];

    float hr = b_hh[d], hz = b_hh[256 + d], hn = b_hh[512 + d];
    float h0v = 0.f;
    if (GH) {
        size_t gho = (size_t)p * GDIM;
        hr += GH[gho + d];
        hz += GH[gho + 256 + d];
        hn += GH[gho + 512 + d];
        h0v = H0[i];
    }
    float r  = sigmf(gr + hr);
    float z  = sigmf(gz + hz);
    float nn = tanhf(gn + r * hn);
    float v = (1.f - z) * nn + z * h0v;
    h1[i] = v;
    h1h[i] = __float2half(v);
}

__global__ void gates2_k(const float* __restrict__ GI, const float* __restrict__ GH,
                         const float* __restrict__ h1,
                         const float* __restrict__ b_ih, const float* __restrict__ b_hh,
                         float* __restrict__ emb_out,   // nullptr except final level
                         float* __restrict__ hs_out,
                         __half* __restrict__ eh, int m)
{
    int i = blockIdx.x * blockDim.x + threadIdx.x;
    int total = BSZ * m * DIM;
    if (i >= total) return;
    int d = i & 255;
    int p = i >> 8;
    int b = p / m, j = p - b * m;

    size_t gio = ((size_t)(b * 2 * m + 2 * j + 1)) * GDIM;
    float gr = GI[gio + d]       + b_ih[d];
    float gz = GI[gio + 256 + d] + b_ih[256 + d];
    float gn = GI[gio + 512 + d] + b_ih[512 + d];

    size_t gho = (size_t)p * GDIM;
    float hr = GH[gho + d]       + b_hh[d];
    float hz = GH[gho + 256 + d] + b_hh[256 + d];
    float hn = GH[gho + 512 + d] + b_hh[512 + d];

    float h1v = h1[i];
    float r  = sigmf(gr + hr);
    float z  = sigmf(gz + hz);
    float nn = tanhf(gn + r * hn);
    float h2 = (1.f - z) * nn + z * h1v;
    hs_out[i]  = h2;
    float ev = 0.5f * (h1v + h2);
    if (emb_out) emb_out[i] = ev;
    eh[i] = __float2half(ev);
}

// ---------------- host orchestration ---------------------------------------
extern "C" void kernel_launch(void* const* d_in, const int* in_sizes, int n_in,
                              void* d_out, int out_size)
{
    const float* leaf = (const float*)d_in[0];
    const float* W_ih = (const float*)d_in[1];
    const float* W_hh = (const float*)d_in[2];
    const float* b_ih = (const float*)d_in[3];
    const float* b_hh = (const float*)d_in[4];
    float* out = (float*)d_out;

    float *p_hs, *p_h0, *p_h1, *p_GI, *p_GH;
    __half *p_lh, *p_eh, *p_h0h, *p_h1h, *p_wihh, *p_whhh;
    { void* p; cudaGetSymbolAddress(&p, g_hs);   p_hs   = (float*)p; }
    { void* p; cudaGetSymbolAddress(&p, g_h0);   p_h0   = (float*)p; }
    { void* p; cudaGetSymbolAddress(&p, g_h1);   p_h1   = (float*)p; }
    { void* p; cudaGetSymbolAddress(&p, g_GI);   p_GI   = (float*)p; }
    { void* p; cudaGetSymbolAddress(&p, g_GH);   p_GH   = (float*)p; }
    { void* p; cudaGetSymbolAddress(&p, g_lh);   p_lh   = (__half*)p; }
    { void* p; cudaGetSymbolAddress(&p, g_eh);   p_eh   = (__half*)p; }
    { void* p; cudaGetSymbolAddress(&p, g_h0h);  p_h0h  = (__half*)p; }
    { void* p; cudaGetSymbolAddress(&p, g_h1h);  p_h1h  = (__half*)p; }
    { void* p; cudaGetSymbolAddress(&p, g_wihh); p_wihh = (__half*)p; }
    { void* p; cudaGetSymbolAddress(&p, g_whhh); p_whhh = (__half*)p; }

    cudaFuncSetAttribute(gemm_f16, cudaFuncAttributeMaxDynamicSharedMemorySize,
                         SMEM_GEMM);

    // convert weights + leaf to fp16
    {
        int n4 = GDIM * DIM / 4;
        cvt_k<<<(n4 + 255) / 256, 256>>>(W_ih, p_wihh, n4);
        cvt_k<<<(n4 + 255) / 256, 256>>>(W_hh, p_whhh, n4);
        int l4 = BSZ * LSEQ * DIM / 4;
        cvt_k<<<(l4 + 255) / 256, 256>>>(leaf, p_lh, l4);
    }

    int n = LSEQ;
    bool have_hs = false;

    while (n > 1) {
        const int m   = n / 2;
        const int Mgi = BSZ * n;
        const int Mh  = BSZ * m;
        const int tot  = Mh * DIM;
        const int tot4 = tot / 4;

        const __half* ah = have_hs ? p_eh : p_lh;

        {   // GI = embeds @ W_ih^T
            dim3 grid((Mgi + TBM - 1) / TBM, GDIM / TBN);
            gemm_f16<<<grid, 128, SMEM_GEMM>>>(ah, p_wihh, p_GI, Mgi);
        }

        if (have_hs) {
            avg_k<<<(tot4 + 255) / 256, 256>>>(p_hs, p_h0, p_h0h, m);
            dim3 grid((Mh + TBM - 1) / TBM, GDIM / TBN);
            gemm_f16<<<grid, 128, SMEM_GEMM>>>(p_h0h, p_whhh, p_GH, Mh);
        }

        gates1_k<<<(tot + 255) / 256, 256>>>(
            p_GI, have_hs ? p_GH : nullptr, have_hs ? p_h0 : nullptr,
            b_ih, b_hh, p_h1, p_h1h, m);

        {
            dim3 grid((Mh + TBM - 1) / TBM, GDIM / TBN);
            gemm_f16<<<grid, 128, SMEM_GEMM>>>(p_h1h, p_whhh, p_GH, Mh);
        }

        gates2_k<<<(tot + 255) / 256, 256>>>(
            p_GI, p_GH, p_h1, b_ih, b_hh,
            (m == 1) ? out : nullptr, p_hs, p_eh, m);

        have_hs = true;
        n = m;
    }
}

// round 9
// speedup vs baseline: 2.9959x; 1.1844x over previous
#include <cuda_runtime.h>
#include <cuda_fp16.h>
#include <cstdint>
#include <math.h>

// Problem constants
#define BSZ 32
#define LSEQ 4096
#define DIM 256
#define GDIM 768   // 3*DIM

// ---------------- scratch (device globals; no allocation allowed) ----------
__device__ float g_hs [BSZ * (LSEQ/2) * DIM];
__device__ float g_h0 [BSZ * (LSEQ/2) * DIM];
__device__ float g_h1 [BSZ * (LSEQ/2) * DIM];
__device__ float g_GI [(size_t)BSZ * LSEQ * GDIM];
__device__ float g_GH [(size_t)BSZ * (LSEQ/2) * GDIM];

// fp16 operand buffers
__device__ __half g_lh  [(size_t)BSZ * LSEQ * DIM];      // leaf fp16
__device__ __half g_eh  [(size_t)BSZ * (LSEQ/2) * DIM];  // emb fp16
__device__ __half g_h0h [(size_t)BSZ * (LSEQ/2) * DIM];
__device__ __half g_h1h [(size_t)BSZ * (LSEQ/2) * DIM];
__device__ __half g_wihh[GDIM * DIM];
__device__ __half g_whhh[GDIM * DIM];

// ======================= helpers ==========================
__device__ __forceinline__ uint32_t smem_u32(const void* p) {
    uint32_t a;
    asm("{ .reg .u64 t; cvta.to.shared.u64 t, %1; cvt.u32.u64 %0, t; }"
        : "=r"(a) : "l"(p));
    return a;
}

__device__ __forceinline__ uint32_t swz(uint32_t b) { return b ^ ((b >> 3) & 0x70); }

__device__ __forceinline__ void cp16(uint32_t dst, const void* src, int sz) {
    asm volatile("cp.async.cg.shared.global [%0], [%1], 16, %2;"
                 :: "r"(dst), "l"(src), "r"(sz));
}

#define CP_COMMIT() asm volatile("cp.async.commit_group;" ::: "memory")
#define CP_WAIT0()  asm volatile("cp.async.wait_group 0;" ::: "memory")

#define LDSM4(R, addr) \
    asm volatile("ldmatrix.sync.aligned.m8n8.x4.shared.b16 {%0,%1,%2,%3}, [%4];" \
        : "=r"((R)[0]), "=r"((R)[1]), "=r"((R)[2]), "=r"((R)[3]) : "r"(addr))

#define MMA_F16(C, A, B0, B1) \
    asm volatile("mma.sync.aligned.m16n8k16.row.col.f32.f16.f16.f32 " \
        "{%0,%1,%2,%3},{%4,%5,%6,%7},{%8,%9},{%0,%1,%2,%3};" \
        : "+f"((C)[0]), "+f"((C)[1]), "+f"((C)[2]), "+f"((C)[3]) \
        : "r"((A)[0]), "r"((A)[1]), "r"((A)[2]), "r"((A)[3]), "r"(B0), "r"(B1))

__device__ __forceinline__ void h4_store(float4 v, __half* __restrict__ dst, size_t idx) {
    __half2 lo = __floats2half2_rn(v.x, v.y);
    __half2 hi = __floats2half2_rn(v.z, v.w);
    *(uint2*)(dst + idx) = make_uint2(*(uint32_t*)&lo, *(uint32_t*)&hi);
}

// ======================= tensor-core GEMM (A-stationary fp16) ===============
// C[M,768] = A[M,256] @ W[768,256]^T.
// CTA: 128 threads, M-tile 128, FULL K=256 of A resident in smem (8 chunked
// 8KB regions, same swizzled layout per chunk). Loops over n_tiles N-tiles of
// 64, streaming 4KB W chunks through a 2-buffer ring. 3 CTAs/SM.
#define TBM 128
#define TBK 32
#define A_OPB 8192               // one A k-chunk: 128 rows * 64 B
#define W_OPB 4096               // one W chunk:    64 rows * 64 B
#define SM_A 0
#define SM_W (8*A_OPB)           // 64 KB
#define SMEM_GEMM (8*A_OPB + 2*W_OPB)   // 72 KB

__global__ void __launch_bounds__(128, 3) gemm_f16(
    const __half* __restrict__ A, const __half* __restrict__ W,
    float* __restrict__ C, int M, int n_tiles)
{
    extern __shared__ char sm[];
    const uint32_t sb = smem_u32(sm);
    const int tid = threadIdx.x;
    const int wid = tid >> 5, lid = tid & 31;
    const int warpM = wid;
    const int bm  = blockIdx.x * TBM;
    const int bn0 = blockIdx.y * n_tiles * 64;

    // A prologue addressing: 1 thread per row, full K (512B = 8 chunks x 64B)
    const int arow = bm + tid;
    const int asz  = (arow < M) ? 16 : 0;
    const int arc  = (arow < M) ? arow : (M - 1);
    const char* Ap = (const char*)(A + (size_t)arc * DIM);
    // W chunk addressing: 2 threads per row
    const uint32_t wd0 = swz((uint32_t)(tid >> 1) * 64 + (tid & 1) * 32);
    const uint32_t wd1 = swz((uint32_t)(tid >> 1) * 64 + (tid & 1) * 32 + 16);

    auto loadW = [&](int c) {   // c = global chunk index: n = c/8, kc = c%8
        const char* Wp = (const char*)(W + (size_t)(bn0 + (c >> 3) * 64 + (tid >> 1)) * DIM);
        uint32_t base = sb + SM_W + (c & 1) * W_OPB;
        const int wgo = (c & 7) * 64 + (tid & 1) * 32;
        cp16(base + wd0, Wp + wgo,      16);
        cp16(base + wd1, Wp + wgo + 16, 16);
    };

    // prologue: all 8 A chunks + W chunk 0 in one group
    #pragma unroll
    for (int kc = 0; kc < 8; kc++) {
        #pragma unroll
        for (int j = 0; j < 4; j++) {
            uint32_t ad = swz((uint32_t)tid * 64 + j * 16);
            cp16(sb + SM_A + kc * A_OPB + ad, Ap + kc * 64 + j * 16, asz);
        }
    }
    loadW(0);
    CP_COMMIT();

    const int q  = lid >> 3;   // ldmatrix quadrant
    const int lq = lid & 7;
    const int total = n_tiles * 8;
    int c = 0;

    #pragma unroll 1
    for (int nt = 0; nt < n_tiles; nt++) {
        float acc[2][8][4];
        #pragma unroll
        for (int a = 0; a < 2; a++)
            #pragma unroll
            for (int b = 0; b < 8; b++)
                #pragma unroll
                for (int d = 0; d < 4; d++) acc[a][b][d] = 0.f;

        #pragma unroll 1
        for (int kc8 = 0; kc8 < 8; kc8++, c++) {
            CP_WAIT0();             // this thread's slice of chunk c done
            __syncthreads();        // everyone's slice done; old buf reads done
            if (c + 1 < total) { loadW(c + 1); CP_COMMIT(); }

            const uint32_t wbase = sb + SM_W + (c & 1) * W_OPB;
            const uint32_t abase = sb + SM_A + (c & 7) * A_OPB;

            #pragma unroll
            for (int ks = 0; ks < 2; ks++) {
                uint32_t bf[4][4];
                #pragma unroll
                for (int np = 0; np < 4; np++) {
                    int r  = np * 16 + ((q >> 1) << 3) + lq;
                    int kb = ks * 32 + ((q & 1) << 4);
                    LDSM4(bf[np], wbase + swz((uint32_t)r * 64 + kb));
                }
                uint32_t af[2][4];
                #pragma unroll
                for (int mt = 0; mt < 2; mt++) {
                    int r  = warpM * 32 + mt * 16 + ((q & 1) << 3) + lq;
                    int kb = ks * 32 + ((q >> 1) << 4);
                    LDSM4(af[mt], abase + swz((uint32_t)r * 64 + kb));
                }
                #pragma unroll
                for (int np = 0; np < 4; np++) {
                    #pragma unroll
                    for (int mt = 0; mt < 2; mt++) {
                        #pragma unroll
                        for (int h = 0; h < 2; h++) {
                            MMA_F16(acc[mt][np*2+h], af[mt], bf[np][h*2], bf[np][h*2+1]);
                        }
                    }
                }
            }
        }

        // epilogue for this N-tile
        const int bn = bn0 + nt * 64;
        #pragma unroll
        for (int mt = 0; mt < 2; mt++) {
            int r0 = bm + warpM * 32 + mt * 16 + (lid >> 2);
            #pragma unroll
            for (int ntc = 0; ntc < 8; ntc++) {
                int col = bn + ntc * 8 + (lid & 3) * 2;
                if (r0 < M)
                    *(float2*)(C + (size_t)r0 * GDIM + col) =
                        make_float2(acc[mt][ntc][0], acc[mt][ntc][1]);
                if (r0 + 8 < M)
                    *(float2*)(C + (size_t)(r0 + 8) * GDIM + col) =
                        make_float2(acc[mt][ntc][2], acc[mt][ntc][3]);
            }
        }
    }
}

// ---------------- elementwise kernels --------------------------------------
__global__ void cvt_k(const float* __restrict__ x, __half* __restrict__ h, int n4)
{
    int i = blockIdx.x * blockDim.x + threadIdx.x;
    if (i >= n4) return;
    float4 v = ((const float4*)x)[i];
    h4_store(v, h, (size_t)i * 4);
}

__global__ void avg_k(const float* __restrict__ hs, float* __restrict__ h0,
                      __half* __restrict__ h0h, int m)
{
    int i = blockIdx.x * blockDim.x + threadIdx.x;
    int total = BSZ * m * (DIM / 4);
    if (i >= total) return;
    int dv = i & 63;
    int p  = i >> 6;
    int b = p / m, j = p - b * m;
    const float4* s0 = (const float4*)hs + ((size_t)(b * 2 * m + 2 * j)) * 64 + dv;
    float4 x = s0[0];
    float4 y = s0[64];
    float4 r = make_float4(0.5f*(x.x+y.x), 0.5f*(x.y+y.y),
                           0.5f*(x.z+y.z), 0.5f*(x.w+y.w));
    ((float4*)h0)[i] = r;
    h4_store(r, h0h, (size_t)i * 4);
}

__device__ __forceinline__ float sigmf(float x) { return 1.f / (1.f + __expf(-x)); }

__global__ void gates1_k(const float* __restrict__ GI, const float* __restrict__ GH,
                         const float* __restrict__ H0,
                         const float* __restrict__ b_ih, const float* __restrict__ b_hh,
                         float* __restrict__ h1, __half* __restrict__ h1h, int m)
{
    int i = blockIdx.x * blockDim.x + threadIdx.x;
    int total = BSZ * m * DIM;
    if (i >= total) return;
    int d = i & 255;
    int p = i >> 8;
    int b = p / m, j = p - b * m;

    size_t gio = ((size_t)(b * 2 * m + 2 * j)) * GDIM;
    float gr = GI[gio + d]       + b_ih[d];
    float gz = GI[gio + 256 + d] + b_ih[256 + d];
    float gn = GI[gio + 512 + d] + b_ih[512 + d];

    float hr = b_hh[d], hz = b_hh[256 + d], hn = b_hh[512 + d];
    float h0v = 0.f;
    if (GH) {
        size_t gho = (size_t)p * GDIM;
        hr += GH[gho + d];
        hz += GH[gho + 256 + d];
        hn += GH[gho + 512 + d];
        h0v = H0[i];
    }
    float r  = sigmf(gr + hr);
    float z  = sigmf(gz + hz);
    float nn = tanhf(gn + r * hn);
    float v = (1.f - z) * nn + z * h0v;
    h1[i] = v;
    h1h[i] = __float2half(v);
}

__global__ void gates2_k(const float* __restrict__ GI, const float* __restrict__ GH,
                         const float* __restrict__ h1,
                         const float* __restrict__ b_ih, const float* __restrict__ b_hh,
                         float* __restrict__ emb_out,   // nullptr except final level
                         float* __restrict__ hs_out,
                         __half* __restrict__ eh, int m)
{
    int i = blockIdx.x * blockDim.x + threadIdx.x;
    int total = BSZ * m * DIM;
    if (i >= total) return;
    int d = i & 255;
    int p = i >> 8;
    int b = p / m, j = p - b * m;

    size_t gio = ((size_t)(b * 2 * m + 2 * j + 1)) * GDIM;
    float gr = GI[gio + d]       + b_ih[d];
    float gz = GI[gio + 256 + d] + b_ih[256 + d];
    float gn = GI[gio + 512 + d] + b_ih[512 + d];

    size_t gho = (size_t)p * GDIM;
    float hr = GH[gho + d]       + b_hh[d];
    float hz = GH[gho + 256 + d] + b_hh[256 + d];
    float hn = GH[gho + 512 + d] + b_hh[512 + d];

    float h1v = h1[i];
    float r  = sigmf(gr + hr);
    float z  = sigmf(gz + hz);
    float nn = tanhf(gn + r * hn);
    float h2 = (1.f - z) * nn + z * h1v;
    hs_out[i]  = h2;
    float ev = 0.5f * (h1v + h2);
    if (emb_out) emb_out[i] = ev;
    eh[i] = __float2half(ev);
}

// ---------------- host orchestration ---------------------------------------
static inline int pick_ntiles(int M) {
    int mb = (M + TBM - 1) / TBM;
    if (mb >= 444) return 6;   // 2 N-groups
    if (mb >= 222) return 3;   // 4 N-groups
    if (mb >= 148) return 2;   // 6 N-groups
    return 1;                  // 12 N-groups
}

extern "C" void kernel_launch(void* const* d_in, const int* in_sizes, int n_in,
                              void* d_out, int out_size)
{
    const float* leaf = (const float*)d_in[0];
    const float* W_ih = (const float*)d_in[1];
    const float* W_hh = (const float*)d_in[2];
    const float* b_ih = (const float*)d_in[3];
    const float* b_hh = (const float*)d_in[4];
    float* out = (float*)d_out;

    float *p_hs, *p_h0, *p_h1, *p_GI, *p_GH;
    __half *p_lh, *p_eh, *p_h0h, *p_h1h, *p_wihh, *p_whhh;
    { void* p; cudaGetSymbolAddress(&p, g_hs);   p_hs   = (float*)p; }
    { void* p; cudaGetSymbolAddress(&p, g_h0);   p_h0   = (float*)p; }
    { void* p; cudaGetSymbolAddress(&p, g_h1);   p_h1   = (float*)p; }
    { void* p; cudaGetSymbolAddress(&p, g_GI);   p_GI   = (float*)p; }
    { void* p; cudaGetSymbolAddress(&p, g_GH);   p_GH   = (float*)p; }
    { void* p; cudaGetSymbolAddress(&p, g_lh);   p_lh   = (__half*)p; }
    { void* p; cudaGetSymbolAddress(&p, g_eh);   p_eh   = (__half*)p; }
    { void* p; cudaGetSymbolAddress(&p, g_h0h);  p_h0h  = (__half*)p; }
    { void* p; cudaGetSymbolAddress(&p, g_h1h);  p_h1h  = (__half*)p; }
    { void* p; cudaGetSymbolAddress(&p, g_wihh); p_wihh = (__half*)p; }
    { void* p; cudaGetSymbolAddress(&p, g_whhh); p_whhh = (__half*)p; }

    cudaFuncSetAttribute(gemm_f16, cudaFuncAttributeMaxDynamicSharedMemorySize,
                         SMEM_GEMM);

    // convert weights + leaf to fp16
    {
        int n4 = GDIM * DIM / 4;
        cvt_k<<<(n4 + 255) / 256, 256>>>(W_ih, p_wihh, n4);
        cvt_k<<<(n4 + 255) / 256, 256>>>(W_hh, p_whhh, n4);
        int l4 = BSZ * LSEQ * DIM / 4;
        cvt_k<<<(l4 + 255) / 256, 256>>>(leaf, p_lh, l4);
    }

    int n = LSEQ;
    bool have_hs = false;

    while (n > 1) {
        const int m   = n / 2;
        const int Mgi = BSZ * n;
        const int Mh  = BSZ * m;
        const int tot  = Mh * DIM;
        const int tot4 = tot / 4;

        const __half* ah = have_hs ? p_eh : p_lh;

        {   // GI = embeds @ W_ih^T
            int nt = pick_ntiles(Mgi);
            dim3 grid((Mgi + TBM - 1) / TBM, 12 / nt);
            gemm_f16<<<grid, 128, SMEM_GEMM>>>(ah, p_wihh, p_GI, Mgi, nt);
        }

        if (have_hs) {
            avg_k<<<(tot4 + 255) / 256, 256>>>(p_hs, p_h0, p_h0h, m);
            int nt = pick_ntiles(Mh);
            dim3 grid((Mh + TBM - 1) / TBM, 12 / nt);
            gemm_f16<<<grid, 128, SMEM_GEMM>>>(p_h0h, p_whhh, p_GH, Mh, nt);
        }

        gates1_k<<<(tot + 255) / 256, 256>>>(
            p_GI, have_hs ? p_GH : nullptr, have_hs ? p_h0 : nullptr,
            b_ih, b_hh, p_h1, p_h1h, m);

        {
            int nt = pick_ntiles(Mh);
            dim3 grid((Mh + TBM - 1) / TBM, 12 / nt);
            gemm_f16<<<grid, 128, SMEM_GEMM>>>(p_h1h, p_whhh, p_GH, Mh, nt);
        }

        gates2_k<<<(tot + 255) / 256, 256>>>(
            p_GI, p_GH, p_h1, b_ih, b_hh,
            (m == 1) ? out : nullptr, p_hs, p_eh, m);

        have_hs = true;
        n = m;
    }
}